// round 15
// baseline (speedup 1.0000x reference)
#include <cuda_runtime.h>
#include <cstdint>
#include <cstddef>

#define NDIM 8192
#define CDIM 16
#define KSEL 131072u
#define MAXDEG 64
#define CAP 512
#define BUF_CAP 33554432u   // 2^25 >= N(N-1)/2 -> full rebuild always fits
#define ENT_CAP 8388608u    // element-entry buffer (overflow -> rebuild)
#define TLOC 10             // per-thread staging (expected 0.67; overflow -> rebuild)
#define LOOP_BLOCKS 148

static constexpr size_t NN = (size_t)NDIM * (size_t)NDIM;
static constexpr size_t NSLOTS = (size_t)NDIM * (size_t)CAP;

// ---------------- device scratch ----------------
__device__ unsigned long long g_buf[BUF_CAP];   // (pBits<<32)|flat candidates
__device__ unsigned int  g_ent[ENT_CAP];        // flat element entries (i*N+j, a1 re-read)
__device__ unsigned int  g_bufCnt, g_entCnt;
__device__ unsigned char g_labels8[NDIM];
__device__ double        g_sameMass, g_totMass;
__device__ float         g_wsame, g_wdiff;
__device__ int           g_skip;
__device__ int           g_rebuild;        // primary collection invalid -> full rescan
__device__ unsigned int  g_maxA;
__device__ unsigned int  g_hist1[4096];
__device__ unsigned int  g_hist2[4096];
__device__ unsigned int  g_hist3[256];
__device__ int           g_nbr[NSLOTS];
__device__ float         g_pf[NSLOTS];
__device__ float         g_pr[NSLOTS];
__device__ unsigned char g_act[NSLOTS];
__device__ int           g_deg[NDIM];
__device__ unsigned int  g_thrU[NDIM];
__device__ unsigned char g_keepall[NDIM];
__device__ unsigned int  g_eqIdx[KSEL];
__device__ unsigned int  g_eqCnt;
__device__ unsigned int  g_changedArr[12];
__device__ unsigned int  g_tk[4];
__device__ unsigned int  g_barCount, g_barGen;

// ---------------- grid barrier (148 co-resident blocks) ----------------
__device__ __forceinline__ void gridBar() {
    __threadfence();
    __syncthreads();
    if (threadIdx.x == 0) {
        unsigned gen = atomicAdd(&g_barGen, 0u);
        if (atomicAdd(&g_barCount, 1u) == LOOP_BLOCKS - 1) {
            g_barCount = 0u;
            __threadfence();
            atomicAdd(&g_barGen, 1u);
        } else {
            unsigned spins = 0;
            while (atomicAdd(&g_barGen, 0u) == gen) {
                if (++spins > (1u << 28)) break;
                __nanosleep(64);
            }
        }
    }
    __syncthreads();
}

// Warp-aggregated global append (RARE paths only: rebuild/complement scans).
__device__ __forceinline__ bool warpAppend(unsigned* counter, bool pred, unsigned cap,
                                           unsigned* outPos, int lane) {
    unsigned bal = __ballot_sync(0xFFFFFFFFu, pred);
    if (!bal) return false;
    unsigned base = 0;
    int leader = __ffs(bal) - 1;
    if (lane == leader) base = atomicAdd(counter, (unsigned)__popc(bal));
    base = __shfl_sync(0xFFFFFFFFu, base, leader);
    if (!pred) return false;
    unsigned pos = base + __popc(bal & ((1u << lane) - 1u));
    *outPos = pos;
    return pos < cap;
}

// Boundary-bin search over 4096 bins, 1024 threads, results into SHARED outputs.
__device__ void scanSelect4096(const unsigned* hist, unsigned baseCum,
                               unsigned* outBin, unsigned* outCntGt) {
    __shared__ unsigned part[1024];
    int t = threadIdx.x;
    unsigned local[4];
    unsigned s = 0;
#pragma unroll
    for (int k = 0; k < 4; k++) { local[k] = __ldcg(&hist[t * 4 + k]); s += local[k]; }
    part[t] = s;
    __syncthreads();
    for (int off = 1; off < 1024; off <<= 1) {
        unsigned v = (t + off < 1024) ? part[t + off] : 0u;
        __syncthreads();
        part[t] += v;
        __syncthreads();
    }
    unsigned cum = baseCum + ((t < 1023) ? part[t + 1] : 0u);
#pragma unroll
    for (int k = 3; k >= 0; k--) {
        unsigned h = local[k];
        unsigned cg = cum + h;
        if (cg >= KSEL && cum < KSEL) { *outBin = (unsigned)(t * 4 + k); *outCntGt = cum; }
        cum = cg;
    }
    __syncthreads();
}

__device__ void scanSelect256(const unsigned* hist, unsigned baseCum, unsigned prefix12,
                              unsigned* outThr, unsigned* outNeed) {
    __shared__ unsigned part2[1024];
    int t = threadIdx.x;
    unsigned h = (t < 256) ? __ldcg(&hist[t]) : 0u;
    part2[t] = h;
    __syncthreads();
    for (int off = 1; off < 1024; off <<= 1) {
        unsigned v = (t + off < 1024) ? part2[t + off] : 0u;
        __syncthreads();
        part2[t] += v;
        __syncthreads();
    }
    unsigned cum = baseCum + ((t < 1023) ? part2[t + 1] : 0u);
    unsigned cg = cum + h;
    if (t < 256 && cg >= KSEL && cum < KSEL) {
        *outThr = (prefix12 << 8) | (unsigned)t;
        *outNeed = KSEL - cum;
    }
    __syncthreads();
}

// ---------------- init: clear (block 32) + argmax (blocks 0..31) ----------------
__global__ void initK(const float* __restrict__ lp) {
    int t = threadIdx.x;
    if (blockIdx.x == 32) {
        for (int k = t; k < 4096; k += 256) { g_hist1[k] = 0; g_hist2[k] = 0; }
        if (t < 256) g_hist3[t] = 0;
        for (int k = t; k < NDIM; k += 256) g_deg[k] = 0;
        if (t < 12) g_changedArr[t] = 0;
        if (t < 4)  g_tk[t] = 0;
        if (t == 0) {
            g_bufCnt = 0; g_entCnt = 0; g_eqCnt = 0; g_maxA = 0; g_rebuild = 0;
            g_sameMass = 0.0; g_totMass = 0.0;
        }
        return;
    }
    int i = blockIdx.x * 256 + t;
    float best = lp[(size_t)i * CDIM];
    int bi = 0;
#pragma unroll
    for (int c = 1; c < CDIM; c++) {
        float v = lp[(size_t)i * CDIM + c];
        if (v > best) { best = v; bi = c; }
    }
    g_labels8[i] = (unsigned char)bi;
}

// ---------------- mass pass + element collection (10x u32 register-staged) ----
// Coverage: a pair with p >= 2.0 has max(a1,a2) >= 0.66666 and, when diff-class
// pairs provably can't reach the pivot, is same-class -> its larger element is
// collected (as a flat index; values re-read at gather). Validity data-driven.
__global__ void massK(const float* __restrict__ adj) {
    __shared__ unsigned char slab[NDIM];
    __shared__ double ssh[256], sth[256];
    __shared__ unsigned smx[256];
    __shared__ unsigned warpTot[8], warpBase[8];
    __shared__ unsigned sBase;
    int i = blockIdx.x, t = threadIdx.x;
    int lane = t & 31, w = t >> 5;
    for (int k = t; k < NDIM / 4; k += 256)
        ((unsigned*)slab)[k] = ((const unsigned*)g_labels8)[k];
    __syncthreads();
    unsigned li4 = (unsigned)slab[i] * 0x01010101u;
    const float4* row = (const float4*)(adj + (size_t)i * NDIM);
    float fs = 0.f, ft = 0.f, fm = 0.f;
    unsigned locEnt[TLOC];
    int cnt = 0;
    for (int q = t; q < NDIM / 4; q += 256) {
        float4 a = __ldcs(&row[q]);
        unsigned l4 = ((unsigned*)slab)[q];
        unsigned eq = __vcmpeq4(l4, li4);
        int j0 = q * 4;
        if (i >= j0 && i < j0 + 4) eq &= ~(0xFFu << ((i - j0) * 8));
        ft += a.x + a.y + a.z + a.w;
        fm = fmaxf(fm, fmaxf(fmaxf(a.x, a.y), fmaxf(a.z, a.w)));
        if (eq & 0x000000FFu) fs += a.x;
        if (eq & 0x0000FF00u) fs += a.y;
        if (eq & 0x00FF0000u) fs += a.z;
        if (eq & 0xFF000000u) fs += a.w;
        float av[4] = {a.x, a.y, a.z, a.w};
#pragma unroll
        for (int k = 0; k < 4; k++) {
            if (((eq >> (8 * k)) & 1u) && av[k] >= 0.6666f) {
                if (cnt < TLOC)
                    locEnt[cnt] = (unsigned)(i * NDIM + j0 + k);
                cnt++;
            }
        }
    }
    if (cnt > TLOC) { g_rebuild = 1; cnt = TLOC; }   // overflow -> exact rescan
    // block scan of cnt, ONE global atomic per block
    unsigned pre = (unsigned)cnt;
    for (int d = 1; d < 32; d <<= 1) {
        unsigned v = __shfl_up_sync(0xFFFFFFFFu, pre, d);
        if (lane >= d) pre += v;
    }
    if (lane == 31) warpTot[w] = pre;
    __syncthreads();
    if (t == 0) {
        unsigned s = 0;
        for (int k = 0; k < 8; k++) { unsigned v = warpTot[k]; warpBase[k] = s; s += v; }
        sBase = s ? atomicAdd(&g_entCnt, s) : 0u;
    }
    __syncthreads();
    {
        unsigned base = sBase + warpBase[w] + (pre - (unsigned)cnt);
        for (int k = 0; k < cnt; k++)
            if (base + k < ENT_CAP) g_ent[base + k] = locEnt[k];
    }
    // mass reduction + ticketed decide
    ssh[t] = (double)fs; sth[t] = (double)ft; smx[t] = __float_as_uint(fmaxf(fm, 0.f));
    __syncthreads();
    for (int off = 128; off > 0; off >>= 1) {
        if (t < off) {
            ssh[t] += ssh[t + off]; sth[t] += sth[t + off];
            smx[t] = max(smx[t], smx[t + off]);
        }
        __syncthreads();
    }
    if (t == 0) {
        atomicAdd(&g_sameMass, ssh[0]);
        atomicAdd(&g_totMass, sth[0]);
        atomicMax(&g_maxA, smx[0]);
        __threadfence();
        if (atomicAdd(&g_tk[0], 1u) == gridDim.x - 1) {
            double sm = g_sameMass, tm = g_totMass;
            double dm = tm - sm;
            float cur = (float)(sm / tm);
            float ws = fminf(fmaxf(0.7f / (cur + 1e-6f), (float)(1.0 / 3.0)), 3.0f);
            float wd = fminf(fmaxf(0.3f / (1.0f - cur + 1e-6f), (float)(1.0 / 3.0)), 3.0f);
            g_wsame = ws; g_wdiff = wd;
            int skip = (sm <= 1e-6 || dm <= 1e-6 || fabsf(cur - 0.7f) <= 0.05f) ? 1 : 0;
            g_skip = skip;
            float maxA = __uint_as_float(g_maxA);
            // only SET (never clear): overflow flags from other blocks must survive
            if (skip || !(__fmul_rn(maxA, wd) < 2.0f)) g_rebuild = 1;
        }
    }
}

__device__ __forceinline__ unsigned pivotBits(int skip) {
    return skip ? 0x3F666666u : 0x40000000u;   // 0.9f : 2.0f
}

// ---------------- edge emission ----------------
__device__ __forceinline__ void emitEdge(int i, int j, float p,
                                         const float* __restrict__ adj, int skip) {
    float pf_i, pr_i, pf_j, pr_j;
    if (skip) {
        float aij = adj[(size_t)i * NDIM + j];
        float aji = adj[(size_t)j * NDIM + i];
        pf_i = aij; pr_i = aji; pf_j = aji; pr_j = aij;
    } else {
        pf_i = pr_i = pf_j = pr_j = p;
    }
    int di = atomicAdd(&g_deg[i], 1);
    if (di < CAP) {
        size_t s = (size_t)i * CAP + di;
        g_nbr[s] = j; g_pf[s] = pf_i; g_pr[s] = pr_i; g_act[s] = 1;
    }
    int dj = atomicAdd(&g_deg[j], 1);
    if (dj < CAP) {
        size_t s = (size_t)j * CAP + dj;
        g_nbr[s] = i; g_pf[s] = pf_j; g_pr[s] = pr_j; g_act[s] = 1;
    }
}

// Full-matrix pair scan appending p to g_buf (RARE: rebuild / complement).
__device__ void scanPairs(const float* __restrict__ adj, int skip, float ws, float wd,
                          int t, bool all, unsigned lo) {
    int lane = t & 31;
    for (int tile = blockIdx.x; tile < 128 * 128; tile += LOOP_BLOCKS) {
        int bi = tile >> 7, bj = tile & 127;
        if (bj < bi) continue;
        for (int e = t; e < 4096; e += 1024) {
            int i = bi * 64 + (e >> 6), j = bj * 64 + (e & 63);
            bool valid = (j > i);
            unsigned bits = 0;
            if (valid) {
                float a1 = adj[(size_t)i * NDIM + j];
                float p;
                if (skip) p = a1;
                else {
                    float a2 = adj[(size_t)j * NDIM + i];
                    float w = (g_labels8[i] == g_labels8[j]) ? ws : wd;
                    p = 0.5f * __fadd_rn(__fmul_rn(a1, w), __fmul_rn(a2, w));
                }
                bits = __float_as_uint(p);
            }
            bool keep = valid && (all || bits < lo);
            unsigned pos;
            if (warpAppend(&g_bufCnt, keep, BUF_CAP, &pos, lane))
                g_buf[pos] = ((unsigned long long)bits << 32) | (unsigned)(i * NDIM + j);
        }
    }
}

// ---------------- persistent tail ----------------
__global__ void __launch_bounds__(1024, 1) postK(const float* __restrict__ adj) {
    __shared__ unsigned shH[4096];
    __shared__ unsigned sWcnt[32], sWbase[32];
    __shared__ unsigned sBlockBase;
    __shared__ unsigned sBA, sCntA, sBinB, sCntB, sBAB, sThr, sNeed;
    int t = threadIdx.x;
    int lane = t & 31, w = t >> 5;
    if (t == 0) { sThr = 0xFFFFFFFFu; sNeed = 0u; }
    __syncthreads();

    int skip = g_skip;
    float ws = g_wsame, wd = g_wdiff;
    unsigned lo = pivotBits(skip);
    unsigned entRaw = __ldcg(&g_entCnt);
    bool rebuild = (__ldcg(&g_rebuild) != 0) || (entRaw > ENT_CAP);

    if (rebuild) {
        scanPairs(adj, skip, ws, wd, t, true, lo);   // exact slow path
    } else {
        // phase G: gather both orientations, emit candidates {p >= lo}
        unsigned entCnt = entRaw;
        for (unsigned cs = blockIdx.x * 1024u; cs < entCnt; cs += LOOP_BLOCKS * 1024u) {
            unsigned e = cs + t;
            bool keep = false;
            unsigned bits = 0, flatC = 0;
            if (e < entCnt) {
                unsigned flat = __ldcg(&g_ent[e]);
                int i = (int)(flat >> 13), j = (int)(flat & 8191u);
                float a1 = __ldg(&adj[(size_t)i * NDIM + j]);
                float a2 = __ldg(&adj[(size_t)j * NDIM + i]);
                // dedup: keep the (a1 >= a2) orientation; ties by i<j
                if (a1 > a2 || (a1 == a2 && i < j)) {
                    float p = 0.5f * __fadd_rn(__fmul_rn(a1, ws), __fmul_rn(a2, ws));
                    bits = __float_as_uint(p);
                    if (bits >= lo) {
                        keep = true;
                        int ii = min(i, j), jj = max(i, j);
                        flatC = (unsigned)(ii * NDIM + jj);
                    }
                }
            }
            unsigned bal = __ballot_sync(0xFFFFFFFFu, keep);
            if (lane == 0) sWcnt[w] = (unsigned)__popc(bal);
            __syncthreads();
            if (t == 0) {
                unsigned s = 0;
                for (int k = 0; k < 32; k++) { unsigned v = sWcnt[k]; sWbase[k] = s; s += v; }
                sBlockBase = s ? atomicAdd(&g_bufCnt, s) : 0u;   // ONE atomic/iteration
            }
            __syncthreads();
            if (keep) {
                unsigned pos = sBlockBase + sWbase[w] + (unsigned)__popc(bal & ((1u << lane) - 1u));
                if (pos < BUF_CAP)
                    g_buf[pos] = ((unsigned long long)bits << 32) | flatC;
            }
            __syncthreads();
        }
    }
    gridBar();

    // phase F: under-collected -> append exact complement {bits < lo}
    if (!rebuild && __ldcg(&g_bufCnt) < KSEL) {
        scanPairs(adj, skip, ws, wd, t, false, lo);
        gridBar();
    }
    unsigned n = min(__ldcg(&g_bufCnt), BUF_CAP);

    // phase H1
    {
        for (int k = t; k < 4096; k += 1024) shH[k] = 0;
        __syncthreads();
        for (unsigned idx = blockIdx.x * 1024u + t; idx < n; idx += LOOP_BLOCKS * 1024u)
            atomicAdd(&shH[(unsigned)(__ldcg(&g_buf[idx]) >> 32) >> 20], 1u);
        __syncthreads();
        for (int k = t; k < 4096; k += 1024)
            if (shH[k]) atomicAdd(&g_hist1[k], shH[k]);
    }
    gridBar();
    scanSelect4096(g_hist1, 0u, &sBA, &sCntA);

    // phase H2
    {
        for (int k = t; k < 4096; k += 1024) shH[k] = 0;
        __syncthreads();
        unsigned bA = sBA;
        for (unsigned idx = blockIdx.x * 1024u + t; idx < n; idx += LOOP_BLOCKS * 1024u) {
            unsigned bits = (unsigned)(__ldcg(&g_buf[idx]) >> 32);
            if ((bits >> 20) == bA) atomicAdd(&shH[(bits >> 8) & 0xFFFu], 1u);
        }
        __syncthreads();
        for (int k = t; k < 4096; k += 1024)
            if (shH[k]) atomicAdd(&g_hist2[k], shH[k]);
    }
    gridBar();
    scanSelect4096(g_hist2, sCntA, &sBinB, &sCntB);
    if (t == 0) sBAB = (sBA << 12) | sBinB;
    __syncthreads();

    // phase H3
    {
        if (t < 256) shH[t] = 0;
        __syncthreads();
        unsigned bAB = sBAB;
        for (unsigned idx = blockIdx.x * 1024u + t; idx < n; idx += LOOP_BLOCKS * 1024u) {
            unsigned bits = (unsigned)(__ldcg(&g_buf[idx]) >> 32);
            if ((bits >> 8) == bAB) atomicAdd(&shH[bits & 0xFFu], 1u);
        }
        __syncthreads();
        if (t < 256 && shH[t]) atomicAdd(&g_hist3[t], shH[t]);
    }
    gridBar();
    scanSelect256(g_hist3, sCntB, sBAB, &sThr, &sNeed);

    // phase S: select + emit
    {
        unsigned thr = sThr;
        for (unsigned idx = blockIdx.x * 1024u + t; idx < n; idx += LOOP_BLOCKS * 1024u) {
            unsigned long long e = __ldcg(&g_buf[idx]);
            unsigned bits = (unsigned)(e >> 32);
            if (bits > thr) {
                unsigned fi = (unsigned)e;
                emitEdge((int)(fi >> 13), (int)(fi & 8191u), __uint_as_float(bits), adj, skip);
            } else if (bits == thr) {
                unsigned pos = atomicAdd(&g_eqCnt, 1u);
                if (pos < KSEL) g_eqIdx[pos] = (unsigned)e;
            }
        }
    }
    gridBar();

    // phase T: tie resolution (lowest flat index wins)
    {
        unsigned M = min(__ldcg(&g_eqCnt), KSEL);
        unsigned need = sNeed;
        unsigned thr = sThr;
        if (need > 0) {
            for (unsigned u = blockIdx.x * 1024u + t; u < M; u += LOOP_BLOCKS * 1024u) {
                unsigned idx = __ldcg(&g_eqIdx[u]);
                unsigned rank = 0;
                for (unsigned s = 0; s < M; s++) rank += (__ldcg(&g_eqIdx[s]) < idx) ? 1u : 0u;
                if (rank < need)
                    emitEdge((int)(idx >> 13), (int)(idx & 8191u), __uint_as_float(thr), adj, skip);
            }
        }
    }
    gridBar();

    // phase P: degree-cap prune loop, warp per row, early exit on fixed point
    int warpG = blockIdx.x * 32 + (t >> 5);
    const int nW = LOOP_BLOCKS * 32;
    __shared__ unsigned sCont;

    for (int iter = 0; iter < 10; iter++) {
        for (int i = warpG; i < NDIM; i += nW) {
            size_t base = (size_t)i * CAP;
            int degE = min(__ldcg(&g_deg[i]), CAP);
            float v[16]; unsigned am = 0, dc = 0;
#pragma unroll
            for (int k = 0; k < 16; k++) {
                int s = lane + k * 32;
                bool a = (s < degE) && (__ldcg(&g_act[base + s]) != 0);
                if (a) { v[k] = __ldcg(&g_pf[base + s]); am |= 1u << k; dc++; }
            }
            unsigned deg = __reduce_add_sync(0xFFFFFFFFu, dc);
            if (deg <= (unsigned)MAXDEG) {
                if (lane == 0) __stcg(&g_keepall[i], (unsigned char)1);
                continue;
            }
            if (lane == 0) __stcg(&g_keepall[i], (unsigned char)0);
            unsigned T = 0;
            for (int b = 31; b >= 0; b--) {
                unsigned cand = T | (1u << b);
                unsigned c = 0;
#pragma unroll
                for (int k = 0; k < 16; k++)
                    if (((am >> k) & 1u) && __float_as_uint(v[k]) >= cand) c++;
                c = __reduce_add_sync(0xFFFFFFFFu, c);
                if (c >= (unsigned)MAXDEG) T = cand;
            }
            if (lane == 0) __stcg(&g_thrU[i], T);
        }
        gridBar();
        bool removed = false;
        for (int i = warpG; i < NDIM; i += nW) {
            size_t base = (size_t)i * CAP;
            int degE = min(__ldcg(&g_deg[i]), CAP);
            unsigned kaI = __ldcg(&g_keepall[i]);
            unsigned thrI = __ldcg(&g_thrU[i]);
            for (int s = lane; s < degE; s += 32) {
                if (!__ldcg(&g_act[base + s])) continue;
                int j = __ldcg(&g_nbr[base + s]);
                bool ki = kaI || (__float_as_uint(__ldcg(&g_pf[base + s])) >= thrI);
                bool kj = __ldcg(&g_keepall[j]) ||
                          (__float_as_uint(__ldcg(&g_pr[base + s])) >= __ldcg(&g_thrU[j]));
                if (!(ki && kj)) { __stcg(&g_act[base + s], (unsigned char)0); removed = true; }
            }
        }
        if (__any_sync(0xFFFFFFFFu, removed) && lane == 0)
            atomicOr(&g_changedArr[iter + 1], 1u);
        gridBar();
        if (t == 0) sCont = __ldcg(&g_changedArr[iter + 1]);
        __syncthreads();
        if (!sCont) break;
    }
}

// ---------------- fused zero + scatter output ----------------
__global__ void outK(float* __restrict__ out) {
    __shared__ unsigned sBits[256];
    int i = blockIdx.x, t = threadIdx.x;
    sBits[t] = 0;
    __syncthreads();
    size_t base = (size_t)i * CAP;
    int degE = min(g_deg[i], CAP);
    for (int s = t; s < degE; s += 256)
        if (g_act[base + s]) {
            int j = g_nbr[base + s];
            atomicOr(&sBits[j >> 5], 1u << (j & 31));
        }
    __syncthreads();
    float4* orow = (float4*)(out + (size_t)i * NDIM);
    for (int q = t; q < NDIM / 4; q += 256) {
        unsigned w = sBits[q >> 3];
        unsigned sh = (q & 7) * 4;
        float4 v;
        v.x = (w >> sh & 1u) ? 1.f : 0.f;
        v.y = (w >> (sh + 1) & 1u) ? 1.f : 0.f;
        v.z = (w >> (sh + 2) & 1u) ? 1.f : 0.f;
        v.w = (w >> (sh + 3) & 1u) ? 1.f : 0.f;
        __stcs(&orow[q], v);
    }
}

// ---------------- launch ----------------
extern "C" void kernel_launch(void* const* d_in, const int* in_sizes, int n_in,
                              void* d_out, int out_size) {
    const float* adj = (const float*)d_in[0];
    const float* lp  = (const float*)d_in[1];
    float* out = (float*)d_out;

    initK<<<33, 256>>>(lp);                    // clear + argmax fused
    massK<<<NDIM, 256>>>(adj);                 // masses + maxA + u32-staged entries + decide
    postK<<<LOOP_BLOCKS, 1024>>>(adj);         // gather/rebuild + radix + select + prune
    outK<<<NDIM, 256>>>(out);
}

// round 16
// speedup vs baseline: 1.0273x; 1.0273x over previous
#include <cuda_runtime.h>
#include <cstdint>
#include <cstddef>

#define NDIM 8192
#define CDIM 16
#define KSEL 131072u
#define MAXDEG 64
#define CAP 512
#define BUF_CAP 33554432u   // 2^25 >= N(N-1)/2 -> full rebuild always fits
#define ENT_CAP 8388608u    // element-entry buffer (overflow -> rebuild)
#define LOOP_BLOCKS 148

static constexpr size_t NN = (size_t)NDIM * (size_t)NDIM;
static constexpr size_t NSLOTS = (size_t)NDIM * (size_t)CAP;

// ---------------- device scratch ----------------
__device__ unsigned long long g_buf[BUF_CAP];   // (pBits<<32)|flat candidates
__device__ unsigned int  g_ent[ENT_CAP];        // flat element entries (values re-read)
__device__ unsigned int  g_bufCnt, g_entCnt;
__device__ unsigned char g_labels8[NDIM];
__device__ double        g_sameMass, g_totMass;
__device__ float         g_wsame, g_wdiff;
__device__ int           g_skip;
__device__ int           g_rebuild;        // primary collection invalid -> full rescan
__device__ unsigned int  g_maxA;
__device__ unsigned int  g_hist1[4096];
__device__ unsigned int  g_hist2[4096];
__device__ unsigned int  g_hist3[256];
__device__ int           g_nbr[NSLOTS];
__device__ float         g_pf[NSLOTS];
__device__ float         g_pr[NSLOTS];
__device__ unsigned char g_act[NSLOTS];
__device__ int           g_deg[NDIM];
__device__ unsigned int  g_thrU[NDIM];
__device__ unsigned char g_keepall[NDIM];
__device__ unsigned int  g_eqIdx[KSEL];
__device__ unsigned int  g_eqCnt;
__device__ unsigned int  g_changedArr[12];
__device__ unsigned int  g_tk[4];
__device__ unsigned int  g_barCount, g_barGen;

// ---------------- grid barrier (148 co-resident blocks) ----------------
__device__ __forceinline__ void gridBar() {
    __threadfence();
    __syncthreads();
    if (threadIdx.x == 0) {
        unsigned gen = atomicAdd(&g_barGen, 0u);
        if (atomicAdd(&g_barCount, 1u) == LOOP_BLOCKS - 1) {
            g_barCount = 0u;
            __threadfence();
            atomicAdd(&g_barGen, 1u);
        } else {
            unsigned spins = 0;
            while (atomicAdd(&g_barGen, 0u) == gen) {
                if (++spins > (1u << 28)) break;
                __nanosleep(64);
            }
        }
    }
    __syncthreads();
}

// Warp-aggregated global append (RARE paths only: rebuild/complement scans).
__device__ __forceinline__ bool warpAppend(unsigned* counter, bool pred, unsigned cap,
                                           unsigned* outPos, int lane) {
    unsigned bal = __ballot_sync(0xFFFFFFFFu, pred);
    if (!bal) return false;
    unsigned base = 0;
    int leader = __ffs(bal) - 1;
    if (lane == leader) base = atomicAdd(counter, (unsigned)__popc(bal));
    base = __shfl_sync(0xFFFFFFFFu, base, leader);
    if (!pred) return false;
    unsigned pos = base + __popc(bal & ((1u << lane) - 1u));
    *outPos = pos;
    return pos < cap;
}

// Boundary-bin search over 4096 bins, 1024 threads, results into SHARED outputs.
__device__ void scanSelect4096(const unsigned* hist, unsigned baseCum,
                               unsigned* outBin, unsigned* outCntGt) {
    __shared__ unsigned part[1024];
    int t = threadIdx.x;
    unsigned local[4];
    unsigned s = 0;
#pragma unroll
    for (int k = 0; k < 4; k++) { local[k] = __ldcg(&hist[t * 4 + k]); s += local[k]; }
    part[t] = s;
    __syncthreads();
    for (int off = 1; off < 1024; off <<= 1) {
        unsigned v = (t + off < 1024) ? part[t + off] : 0u;
        __syncthreads();
        part[t] += v;
        __syncthreads();
    }
    unsigned cum = baseCum + ((t < 1023) ? part[t + 1] : 0u);
#pragma unroll
    for (int k = 3; k >= 0; k--) {
        unsigned h = local[k];
        unsigned cg = cum + h;
        if (cg >= KSEL && cum < KSEL) { *outBin = (unsigned)(t * 4 + k); *outCntGt = cum; }
        cum = cg;
    }
    __syncthreads();
}

__device__ void scanSelect256(const unsigned* hist, unsigned baseCum, unsigned prefix12,
                              unsigned* outThr, unsigned* outNeed) {
    __shared__ unsigned part2[1024];
    int t = threadIdx.x;
    unsigned h = (t < 256) ? __ldcg(&hist[t]) : 0u;
    part2[t] = h;
    __syncthreads();
    for (int off = 1; off < 1024; off <<= 1) {
        unsigned v = (t + off < 1024) ? part2[t + off] : 0u;
        __syncthreads();
        part2[t] += v;
        __syncthreads();
    }
    unsigned cum = baseCum + ((t < 1023) ? part2[t + 1] : 0u);
    unsigned cg = cum + h;
    if (t < 256 && cg >= KSEL && cum < KSEL) {
        *outThr = (prefix12 << 8) | (unsigned)t;
        *outNeed = KSEL - cum;
    }
    __syncthreads();
}

// ---------------- init: clear (block 32) + argmax (blocks 0..31) ----------------
__global__ void initK(const float* __restrict__ lp) {
    int t = threadIdx.x;
    if (blockIdx.x == 32) {
        for (int k = t; k < 4096; k += 256) { g_hist1[k] = 0; g_hist2[k] = 0; }
        if (t < 256) g_hist3[t] = 0;
        for (int k = t; k < NDIM; k += 256) g_deg[k] = 0;
        if (t < 12) g_changedArr[t] = 0;
        if (t < 4)  g_tk[t] = 0;
        if (t == 0) {
            g_bufCnt = 0; g_entCnt = 0; g_eqCnt = 0; g_maxA = 0; g_rebuild = 0;
            g_sameMass = 0.0; g_totMass = 0.0;
        }
        return;
    }
    int i = blockIdx.x * 256 + t;
    float best = lp[(size_t)i * CDIM];
    int bi = 0;
#pragma unroll
    for (int c = 1; c < CDIM; c++) {
        float v = lp[(size_t)i * CDIM + c];
        if (v > best) { best = v; bi = c; }
    }
    g_labels8[i] = (unsigned char)bi;
}

// ---------------- mass pass + element collection (1-bit-per-element mask) ----
// Each thread covers exactly 32 elements (8 unrolled float4 groups); the
// collection predicate is ONE bit in pm -> zero hot-loop arrays/counters.
// Coverage: a pair with p >= 2.0 has max(a1,a2) >= 0.66666 and (validated via
// g_rebuild) is same-class -> its larger element is recorded here.
__global__ void massK(const float* __restrict__ adj) {
    __shared__ unsigned char slab[NDIM];
    __shared__ double ssh[256], sth[256];
    __shared__ unsigned smx[256];
    __shared__ unsigned warpTot[8], warpBase[8];
    __shared__ unsigned sBase;
    int i = blockIdx.x, t = threadIdx.x;
    int lane = t & 31, w = t >> 5;
    for (int k = t; k < NDIM / 4; k += 256)
        ((unsigned*)slab)[k] = ((const unsigned*)g_labels8)[k];
    __syncthreads();
    unsigned li4 = (unsigned)slab[i] * 0x01010101u;
    const float4* row = (const float4*)(adj + (size_t)i * NDIM);
    float fs = 0.f, ft = 0.f, fm = 0.f;
    unsigned pm = 0;
#pragma unroll
    for (int r = 0; r < 8; r++) {
        int q = t + r * 256;
        float4 a = __ldcs(&row[q]);
        unsigned l4 = ((unsigned*)slab)[q];
        unsigned eq = __vcmpeq4(l4, li4);
        int j0 = q * 4;
        if (i >= j0 && i < j0 + 4) eq &= ~(0xFFu << ((i - j0) * 8));
        ft += a.x + a.y + a.z + a.w;
        fm = fmaxf(fm, fmaxf(fmaxf(a.x, a.y), fmaxf(a.z, a.w)));
        if (eq & 0x000000FFu) fs += a.x;
        if (eq & 0x0000FF00u) fs += a.y;
        if (eq & 0x00FF0000u) fs += a.z;
        if (eq & 0xFF000000u) fs += a.w;
        float av[4] = {a.x, a.y, a.z, a.w};
#pragma unroll
        for (int k = 0; k < 4; k++)
            if (av[k] >= 0.6666f && (eq & (1u << (8 * k))))
                pm |= 1u << (r * 4 + k);
    }
    int cnt = __popc(pm);
    // block scan of cnt, ONE global atomic per block
    unsigned pre = (unsigned)cnt;
    for (int d = 1; d < 32; d <<= 1) {
        unsigned v = __shfl_up_sync(0xFFFFFFFFu, pre, d);
        if (lane >= d) pre += v;
    }
    if (lane == 31) warpTot[w] = pre;
    __syncthreads();
    if (t == 0) {
        unsigned s = 0;
        for (int k = 0; k < 8; k++) { unsigned v = warpTot[k]; warpBase[k] = s; s += v; }
        sBase = s ? atomicAdd(&g_entCnt, s) : 0u;
    }
    __syncthreads();
    {
        unsigned base = sBase + warpBase[w] + (pre - (unsigned)cnt);
        unsigned mm = pm;
        while (mm) {
            int b = __ffs(mm) - 1;
            mm &= mm - 1;
            int r = b >> 2, k = b & 3;
            if (base < ENT_CAP)
                g_ent[base] = (unsigned)(i * NDIM + (t + r * 256) * 4 + k);
            base++;
        }
    }
    // mass reduction + ticketed decide
    ssh[t] = (double)fs; sth[t] = (double)ft; smx[t] = __float_as_uint(fmaxf(fm, 0.f));
    __syncthreads();
    for (int off = 128; off > 0; off >>= 1) {
        if (t < off) {
            ssh[t] += ssh[t + off]; sth[t] += sth[t + off];
            smx[t] = max(smx[t], smx[t + off]);
        }
        __syncthreads();
    }
    if (t == 0) {
        atomicAdd(&g_sameMass, ssh[0]);
        atomicAdd(&g_totMass, sth[0]);
        atomicMax(&g_maxA, smx[0]);
        __threadfence();
        if (atomicAdd(&g_tk[0], 1u) == gridDim.x - 1) {
            double sm = g_sameMass, tm = g_totMass;
            double dm = tm - sm;
            float cur = (float)(sm / tm);
            float ws = fminf(fmaxf(0.7f / (cur + 1e-6f), (float)(1.0 / 3.0)), 3.0f);
            float wd = fminf(fmaxf(0.3f / (1.0f - cur + 1e-6f), (float)(1.0 / 3.0)), 3.0f);
            g_wsame = ws; g_wdiff = wd;
            int skip = (sm <= 1e-6 || dm <= 1e-6 || fabsf(cur - 0.7f) <= 0.05f) ? 1 : 0;
            g_skip = skip;
            float maxA = __uint_as_float(g_maxA);
            // only SET (never clear)
            if (skip || !(__fmul_rn(maxA, wd) < 2.0f)) g_rebuild = 1;
        }
    }
}

__device__ __forceinline__ unsigned pivotBits(int skip) {
    return skip ? 0x3F666666u : 0x40000000u;   // 0.9f : 2.0f
}

// ---------------- edge emission ----------------
__device__ __forceinline__ void emitEdge(int i, int j, float p,
                                         const float* __restrict__ adj, int skip) {
    float pf_i, pr_i, pf_j, pr_j;
    if (skip) {
        float aij = adj[(size_t)i * NDIM + j];
        float aji = adj[(size_t)j * NDIM + i];
        pf_i = aij; pr_i = aji; pf_j = aji; pr_j = aij;
    } else {
        pf_i = pr_i = pf_j = pr_j = p;
    }
    int di = atomicAdd(&g_deg[i], 1);
    if (di < CAP) {
        size_t s = (size_t)i * CAP + di;
        g_nbr[s] = j; g_pf[s] = pf_i; g_pr[s] = pr_i; g_act[s] = 1;
    }
    int dj = atomicAdd(&g_deg[j], 1);
    if (dj < CAP) {
        size_t s = (size_t)j * CAP + dj;
        g_nbr[s] = i; g_pf[s] = pf_j; g_pr[s] = pr_j; g_act[s] = 1;
    }
}

// Full-matrix pair scan appending p to g_buf (RARE: rebuild / complement).
__device__ void scanPairs(const float* __restrict__ adj, int skip, float ws, float wd,
                          int t, bool all, unsigned lo) {
    int lane = t & 31;
    for (int tile = blockIdx.x; tile < 128 * 128; tile += LOOP_BLOCKS) {
        int bi = tile >> 7, bj = tile & 127;
        if (bj < bi) continue;
        for (int e = t; e < 4096; e += 1024) {
            int i = bi * 64 + (e >> 6), j = bj * 64 + (e & 63);
            bool valid = (j > i);
            unsigned bits = 0;
            if (valid) {
                float a1 = adj[(size_t)i * NDIM + j];
                float p;
                if (skip) p = a1;
                else {
                    float a2 = adj[(size_t)j * NDIM + i];
                    float w = (g_labels8[i] == g_labels8[j]) ? ws : wd;
                    p = 0.5f * __fadd_rn(__fmul_rn(a1, w), __fmul_rn(a2, w));
                }
                bits = __float_as_uint(p);
            }
            bool keep = valid && (all || bits < lo);
            unsigned pos;
            if (warpAppend(&g_bufCnt, keep, BUF_CAP, &pos, lane))
                g_buf[pos] = ((unsigned long long)bits << 32) | (unsigned)(i * NDIM + j);
        }
    }
}

// ---------------- persistent tail ----------------
__global__ void __launch_bounds__(1024, 1) postK(const float* __restrict__ adj) {
    __shared__ unsigned shH[4096];
    __shared__ unsigned sWcnt[32], sWbase[32];
    __shared__ unsigned sBlockBase;
    __shared__ unsigned sBA, sCntA, sBinB, sCntB, sBAB, sThr, sNeed;
    int t = threadIdx.x;
    int lane = t & 31, w = t >> 5;
    if (t == 0) { sThr = 0xFFFFFFFFu; sNeed = 0u; }
    __syncthreads();

    int skip = g_skip;
    float ws = g_wsame, wd = g_wdiff;
    unsigned lo = pivotBits(skip);
    unsigned entRaw = __ldcg(&g_entCnt);
    bool rebuild = (__ldcg(&g_rebuild) != 0) || (entRaw > ENT_CAP);

    if (rebuild) {
        scanPairs(adj, skip, ws, wd, t, true, lo);   // exact slow path
    } else {
        // phase G: gather both orientations, emit candidates {p >= lo}
        unsigned entCnt = entRaw;
        for (unsigned cs = blockIdx.x * 1024u; cs < entCnt; cs += LOOP_BLOCKS * 1024u) {
            unsigned e = cs + t;
            bool keep = false;
            unsigned bits = 0, flatC = 0;
            if (e < entCnt) {
                unsigned flat = __ldcg(&g_ent[e]);
                int i = (int)(flat >> 13), j = (int)(flat & 8191u);
                float a1 = __ldg(&adj[(size_t)i * NDIM + j]);
                float a2 = __ldg(&adj[(size_t)j * NDIM + i]);
                // dedup: keep the (a1 >= a2) orientation; ties by i<j
                if (a1 > a2 || (a1 == a2 && i < j)) {
                    float p = 0.5f * __fadd_rn(__fmul_rn(a1, ws), __fmul_rn(a2, ws));
                    bits = __float_as_uint(p);
                    if (bits >= lo) {
                        keep = true;
                        int ii = min(i, j), jj = max(i, j);
                        flatC = (unsigned)(ii * NDIM + jj);
                    }
                }
            }
            unsigned bal = __ballot_sync(0xFFFFFFFFu, keep);
            if (lane == 0) sWcnt[w] = (unsigned)__popc(bal);
            __syncthreads();
            if (t == 0) {
                unsigned s = 0;
                for (int k = 0; k < 32; k++) { unsigned v = sWcnt[k]; sWbase[k] = s; s += v; }
                sBlockBase = s ? atomicAdd(&g_bufCnt, s) : 0u;   // ONE atomic/iteration
            }
            __syncthreads();
            if (keep) {
                unsigned pos = sBlockBase + sWbase[w] + (unsigned)__popc(bal & ((1u << lane) - 1u));
                if (pos < BUF_CAP)
                    g_buf[pos] = ((unsigned long long)bits << 32) | flatC;
            }
            __syncthreads();
        }
    }
    gridBar();

    // phase F: under-collected -> append exact complement {bits < lo}
    if (!rebuild && __ldcg(&g_bufCnt) < KSEL) {
        scanPairs(adj, skip, ws, wd, t, false, lo);
        gridBar();
    }
    unsigned n = min(__ldcg(&g_bufCnt), BUF_CAP);

    // phase H1
    {
        for (int k = t; k < 4096; k += 1024) shH[k] = 0;
        __syncthreads();
        for (unsigned idx = blockIdx.x * 1024u + t; idx < n; idx += LOOP_BLOCKS * 1024u)
            atomicAdd(&shH[(unsigned)(__ldcg(&g_buf[idx]) >> 32) >> 20], 1u);
        __syncthreads();
        for (int k = t; k < 4096; k += 1024)
            if (shH[k]) atomicAdd(&g_hist1[k], shH[k]);
    }
    gridBar();
    scanSelect4096(g_hist1, 0u, &sBA, &sCntA);

    // phase H2
    {
        for (int k = t; k < 4096; k += 1024) shH[k] = 0;
        __syncthreads();
        unsigned bA = sBA;
        for (unsigned idx = blockIdx.x * 1024u + t; idx < n; idx += LOOP_BLOCKS * 1024u) {
            unsigned bits = (unsigned)(__ldcg(&g_buf[idx]) >> 32);
            if ((bits >> 20) == bA) atomicAdd(&shH[(bits >> 8) & 0xFFFu], 1u);
        }
        __syncthreads();
        for (int k = t; k < 4096; k += 1024)
            if (shH[k]) atomicAdd(&g_hist2[k], shH[k]);
    }
    gridBar();
    scanSelect4096(g_hist2, sCntA, &sBinB, &sCntB);
    if (t == 0) sBAB = (sBA << 12) | sBinB;
    __syncthreads();

    // phase H3
    {
        if (t < 256) shH[t] = 0;
        __syncthreads();
        unsigned bAB = sBAB;
        for (unsigned idx = blockIdx.x * 1024u + t; idx < n; idx += LOOP_BLOCKS * 1024u) {
            unsigned bits = (unsigned)(__ldcg(&g_buf[idx]) >> 32);
            if ((bits >> 8) == bAB) atomicAdd(&shH[bits & 0xFFu], 1u);
        }
        __syncthreads();
        if (t < 256 && shH[t]) atomicAdd(&g_hist3[t], shH[t]);
    }
    gridBar();
    scanSelect256(g_hist3, sCntB, sBAB, &sThr, &sNeed);

    // phase S: select + emit
    {
        unsigned thr = sThr;
        for (unsigned idx = blockIdx.x * 1024u + t; idx < n; idx += LOOP_BLOCKS * 1024u) {
            unsigned long long e = __ldcg(&g_buf[idx]);
            unsigned bits = (unsigned)(e >> 32);
            if (bits > thr) {
                unsigned fi = (unsigned)e;
                emitEdge((int)(fi >> 13), (int)(fi & 8191u), __uint_as_float(bits), adj, skip);
            } else if (bits == thr) {
                unsigned pos = atomicAdd(&g_eqCnt, 1u);
                if (pos < KSEL) g_eqIdx[pos] = (unsigned)e;
            }
        }
    }
    gridBar();

    // phase T: tie resolution (lowest flat index wins)
    {
        unsigned M = min(__ldcg(&g_eqCnt), KSEL);
        unsigned need = sNeed;
        unsigned thr = sThr;
        if (need > 0) {
            for (unsigned u = blockIdx.x * 1024u + t; u < M; u += LOOP_BLOCKS * 1024u) {
                unsigned idx = __ldcg(&g_eqIdx[u]);
                unsigned rank = 0;
                for (unsigned s = 0; s < M; s++) rank += (__ldcg(&g_eqIdx[s]) < idx) ? 1u : 0u;
                if (rank < need)
                    emitEdge((int)(idx >> 13), (int)(idx & 8191u), __uint_as_float(thr), adj, skip);
            }
        }
    }
    gridBar();

    // phase P: degree-cap prune loop, warp per row, early exit on fixed point
    int warpG = blockIdx.x * 32 + (t >> 5);
    const int nW = LOOP_BLOCKS * 32;
    __shared__ unsigned sCont;

    for (int iter = 0; iter < 10; iter++) {
        for (int i = warpG; i < NDIM; i += nW) {
            size_t base = (size_t)i * CAP;
            int degE = min(__ldcg(&g_deg[i]), CAP);
            float v[16]; unsigned am = 0, dc = 0;
#pragma unroll
            for (int k = 0; k < 16; k++) {
                int s = lane + k * 32;
                bool a = (s < degE) && (__ldcg(&g_act[base + s]) != 0);
                if (a) { v[k] = __ldcg(&g_pf[base + s]); am |= 1u << k; dc++; }
            }
            unsigned deg = __reduce_add_sync(0xFFFFFFFFu, dc);
            if (deg <= (unsigned)MAXDEG) {
                if (lane == 0) __stcg(&g_keepall[i], (unsigned char)1);
                continue;
            }
            if (lane == 0) __stcg(&g_keepall[i], (unsigned char)0);
            unsigned T = 0;
            for (int b = 31; b >= 0; b--) {
                unsigned cand = T | (1u << b);
                unsigned c = 0;
#pragma unroll
                for (int k = 0; k < 16; k++)
                    if (((am >> k) & 1u) && __float_as_uint(v[k]) >= cand) c++;
                c = __reduce_add_sync(0xFFFFFFFFu, c);
                if (c >= (unsigned)MAXDEG) T = cand;
            }
            if (lane == 0) __stcg(&g_thrU[i], T);
        }
        gridBar();
        bool removed = false;
        for (int i = warpG; i < NDIM; i += nW) {
            size_t base = (size_t)i * CAP;
            int degE = min(__ldcg(&g_deg[i]), CAP);
            unsigned kaI = __ldcg(&g_keepall[i]);
            unsigned thrI = __ldcg(&g_thrU[i]);
            for (int s = lane; s < degE; s += 32) {
                if (!__ldcg(&g_act[base + s])) continue;
                int j = __ldcg(&g_nbr[base + s]);
                bool ki = kaI || (__float_as_uint(__ldcg(&g_pf[base + s])) >= thrI);
                bool kj = __ldcg(&g_keepall[j]) ||
                          (__float_as_uint(__ldcg(&g_pr[base + s])) >= __ldcg(&g_thrU[j]));
                if (!(ki && kj)) { __stcg(&g_act[base + s], (unsigned char)0); removed = true; }
            }
        }
        if (__any_sync(0xFFFFFFFFu, removed) && lane == 0)
            atomicOr(&g_changedArr[iter + 1], 1u);
        gridBar();
        if (t == 0) sCont = __ldcg(&g_changedArr[iter + 1]);
        __syncthreads();
        if (!sCont) break;
    }
}

// ---------------- fused zero + scatter output ----------------
__global__ void outK(float* __restrict__ out) {
    __shared__ unsigned sBits[256];
    int i = blockIdx.x, t = threadIdx.x;
    sBits[t] = 0;
    __syncthreads();
    size_t base = (size_t)i * CAP;
    int degE = min(g_deg[i], CAP);
    for (int s = t; s < degE; s += 256)
        if (g_act[base + s]) {
            int j = g_nbr[base + s];
            atomicOr(&sBits[j >> 5], 1u << (j & 31));
        }
    __syncthreads();
    float4* orow = (float4*)(out + (size_t)i * NDIM);
    for (int q = t; q < NDIM / 4; q += 256) {
        unsigned w = sBits[q >> 3];
        unsigned sh = (q & 7) * 4;
        float4 v;
        v.x = (w >> sh & 1u) ? 1.f : 0.f;
        v.y = (w >> (sh + 1) & 1u) ? 1.f : 0.f;
        v.z = (w >> (sh + 2) & 1u) ? 1.f : 0.f;
        v.w = (w >> (sh + 3) & 1u) ? 1.f : 0.f;
        __stcs(&orow[q], v);
    }
}

// ---------------- launch ----------------
extern "C" void kernel_launch(void* const* d_in, const int* in_sizes, int n_in,
                              void* d_out, int out_size) {
    const float* adj = (const float*)d_in[0];
    const float* lp  = (const float*)d_in[1];
    float* out = (float*)d_out;

    initK<<<33, 256>>>(lp);                    // clear + argmax fused
    massK<<<NDIM, 256>>>(adj);                 // masses + maxA + bitmask entries + decide
    postK<<<LOOP_BLOCKS, 1024>>>(adj);         // gather/rebuild + radix + select + prune
    outK<<<NDIM, 256>>>(out);
}